// round 15
// baseline (speedup 1.0000x reference)
#include <cuda_runtime.h>
#include <cuda_bf16.h>
#include <cstdint>

#define BB 2
#define SS 2048
#define DD 1024
#define HH 16
#define HDD 64
#define MM (BB * SS)   // 4096

// ---------------------------------------------------------------------------
// Arch-specific gate: tcgen05 exists only on sm_10xa targets.
// ---------------------------------------------------------------------------
#if defined(__CUDA_ARCH__) && (__CUDA_ARCH__ >= 1000)
#  if defined(__CUDA_ARCH_HAS_FEATURE__)
#    if __CUDA_ARCH_HAS_FEATURE__(SM103_ALL) || __CUDA_ARCH_HAS_FEATURE__(SM100_ALL) || __CUDA_ARCH_HAS_FEATURE__(SM101_ALL)
#      define HAS_TCGEN05 1
#    endif
#  endif
#  if !defined(HAS_TCGEN05) && defined(__CUDA_ARCH_SPECIFIC__)
#    define HAS_TCGEN05 1
#  endif
#  if !defined(HAS_TCGEN05) && defined(__CUDA_ARCH_FEAT_SM103_ALL)
#    define HAS_TCGEN05 1
#  endif
#  if !defined(HAS_TCGEN05) && defined(__CUDA_ARCH_FEAT_SM100_ALL)
#    define HAS_TCGEN05 1
#  endif
#endif

// ---------------------------------------------------------------------------
// Scratch (device globals; allocation is forbidden)
// ---------------------------------------------------------------------------
__device__ float g_q[(size_t)BB * HH * SS * HDD];
__device__ float g_k[(size_t)BB * HH * SS * HDD];
__device__ float g_v[(size_t)BB * HH * SS * HDD];
__device__ float g_att[(size_t)BB * SS * DD];
__device__ float g_P[(size_t)BB * HH * SS * SS];
__device__ __nv_bfloat16 g_ah[(size_t)MM * DD];
__device__ __nv_bfloat16 g_al[(size_t)MM * DD];
__device__ __nv_bfloat16 g_wh[(size_t)DD * DD];
__device__ __nv_bfloat16 g_wl[(size_t)DD * DD];

#ifdef HAS_TCGEN05
// ---------------------------------------------------------------------------
// PTX helpers
// ---------------------------------------------------------------------------
__device__ __forceinline__ uint32_t smem_u32(const void* p) {
    uint32_t a;
    asm("{ .reg .u64 t; cvta.to.shared.u64 t, %1; cvt.u32.u64 %0, t; }"
        : "=r"(a) : "l"(p));
    return a;
}
__device__ __forceinline__ uint32_t elect1() {
    uint32_t pred;
    asm volatile(
        "{ .reg .pred p; elect.sync _|p, 0xFFFFFFFF; selp.b32 %0, 1, 0, p; }"
        : "=r"(pred));
    return pred;
}

#define TC_ALLOC(smem_addr, ncols) \
    asm volatile("tcgen05.alloc.cta_group::1.sync.aligned.shared::cta.b32 [%0], %1;" \
                 :: "r"(smem_addr), "r"((uint32_t)(ncols)) : "memory")
#define TC_RELINQ() \
    asm volatile("tcgen05.relinquish_alloc_permit.cta_group::1.sync.aligned;")
#define TC_DEALLOC(tmem, ncols) \
    asm volatile("tcgen05.dealloc.cta_group::1.sync.aligned.b32 %0, %1;" \
                 :: "r"(tmem), "r"((uint32_t)(ncols)))
#define TC_COMMIT(mbar) \
    asm volatile("tcgen05.commit.cta_group::1.mbarrier::arrive::one.shared::cluster.b64 [%0];" \
                 :: "r"(mbar) : "memory")
#define TC_FENCE_AFTER() \
    asm volatile("tcgen05.fence::after_thread_sync;" ::: "memory")
#define TC_FENCE_BEFORE() \
    asm volatile("tcgen05.fence::before_thread_sync;" ::: "memory")
#define TC_WAIT_LD() \
    asm volatile("tcgen05.wait::ld.sync.aligned;" ::: "memory")
#define FENCE_ASYNC_SHARED() \
    asm volatile("fence.proxy.async.shared::cta;" ::: "memory")
#define MBAR_INIT(mbar, cnt) \
    asm volatile("mbarrier.init.shared.b64 [%0], %1;" \
                 :: "r"(mbar), "r"((uint32_t)(cnt)) : "memory")
#define MBAR_INVAL(mbar) \
    asm volatile("mbarrier.inval.shared.b64 [%0];" :: "r"(mbar) : "memory")

#define MBAR_WAIT_PARITY(mbar_a, par) do {                                      \
    uint32_t _m = (mbar_a); uint32_t _p = (par); uint32_t _d;                   \
    asm volatile(                                                               \
        "{\n\t.reg .pred p;\n\t"                                                \
        "mbarrier.try_wait.parity.acquire.cta.shared::cta.b64 p, [%1], %2;\n\t" \
        "selp.b32 %0, 1, 0, p;\n\t}"                                            \
        : "=r"(_d) : "r"(_m), "r"(_p) : "memory");                              \
    if (!_d) {                                                                  \
        asm volatile(                                                           \
            "{\n\t.reg .pred P1;\n\t"                                           \
            "WL_%=:\n\t"                                                        \
            "mbarrier.try_wait.parity.acquire.cta.shared::cta.b64 P1, [%0], %1, 0x989680;\n\t" \
            "@P1 bra.uni WD_%=;\n\t"                                            \
            "bra.uni WL_%=;\n\t"                                                \
            "WD_%=:\n\t}"                                                       \
            :: "r"(_m), "r"(_p) : "memory");                                    \
    }                                                                           \
} while (0)

#define TC_LD_32X32B_X32(r, tmem_addr) \
    asm volatile( \
        "tcgen05.ld.sync.aligned.32x32b.x32.b32 " \
        "{%0, %1, %2, %3, %4, %5, %6, %7, " \
        " %8, %9, %10, %11, %12, %13, %14, %15, " \
        " %16, %17, %18, %19, %20, %21, %22, %23, " \
        " %24, %25, %26, %27, %28, %29, %30, %31}, [%32];" \
        : "=r"((r)[0]),  "=r"((r)[1]),  "=r"((r)[2]),  "=r"((r)[3]), \
          "=r"((r)[4]),  "=r"((r)[5]),  "=r"((r)[6]),  "=r"((r)[7]), \
          "=r"((r)[8]),  "=r"((r)[9]),  "=r"((r)[10]), "=r"((r)[11]), \
          "=r"((r)[12]), "=r"((r)[13]), "=r"((r)[14]), "=r"((r)[15]), \
          "=r"((r)[16]), "=r"((r)[17]), "=r"((r)[18]), "=r"((r)[19]), \
          "=r"((r)[20]), "=r"((r)[21]), "=r"((r)[22]), "=r"((r)[23]), \
          "=r"((r)[24]), "=r"((r)[25]), "=r"((r)[26]), "=r"((r)[27]), \
          "=r"((r)[28]), "=r"((r)[29]), "=r"((r)[30]), "=r"((r)[31]) \
        : "r"(tmem_addr))

__device__ __forceinline__ void mma_bf16_ss(
    uint32_t d, uint64_t da, uint64_t db, uint32_t idesc, uint32_t en)
{
    asm volatile(
        "{\n\t"
        ".reg .pred p;\n\t"
        "setp.ne.u32 p, %5, 0;\n\t"
        "tcgen05.mma.cta_group::1.kind::f16 [%0], %1, %2, %3, {%4, %4, %4, %4}, p;\n\t"
        "}"
        :: "r"(d), "l"(da), "l"(db), "r"(idesc), "r"(0u), "r"(en)
        : "memory");
}

static __device__ __forceinline__ uint64_t make_desc(uint32_t addr) {
    const uint64_t base =
        (uint64_t(2) << 61) | (uint64_t(1) << 46) |
        (uint64_t(64) << 32) | (uint64_t(1) << 16);
    return base | ((uint64_t)(addr >> 4) & 0x3FFF);
}

#define SMZ(off) ((off) ^ (((off) >> 3) & 0x70))

// idesc: f32 acc, bf16 a/b
#define GT_IDESC ((1u << 4) | (1u << 7) | (1u << 10) | ((128u / 8) << 17) | ((128u / 16) << 24))  // M=128,N=128
#define AT_IDESC ((1u << 4) | (1u << 7) | (1u << 10) | ((64u / 8) << 17) | ((128u / 16) << 24))   // M=128,N=64
#endif  // HAS_TCGEN05

// ---------------------------------------------------------------------------
// split: x(fp32) -> hi, lo (bf16)
// ---------------------------------------------------------------------------
__global__ __launch_bounds__(256) void split_kernel(
    const float* __restrict__ x, __nv_bfloat16* __restrict__ hi,
    __nv_bfloat16* __restrict__ lo, int n)
{
    const int stride = gridDim.x * blockDim.x * 4;
    for (int i = (blockIdx.x * blockDim.x + threadIdx.x) * 4; i < n; i += stride) {
        float4 v = *(const float4*)(x + i);
        __nv_bfloat16 h0 = __float2bfloat16(v.x);
        __nv_bfloat16 h1 = __float2bfloat16(v.y);
        __nv_bfloat16 h2 = __float2bfloat16(v.z);
        __nv_bfloat16 h3 = __float2bfloat16(v.w);
        __nv_bfloat162 hp0; hp0.x = h0; hp0.y = h1;
        __nv_bfloat162 hp1; hp1.x = h2; hp1.y = h3;
        *(__nv_bfloat162*)(hi + i)     = hp0;
        *(__nv_bfloat162*)(hi + i + 2) = hp1;
        __nv_bfloat162 lp0, lp1;
        lp0.x = __float2bfloat16(v.x - __bfloat162float(h0));
        lp0.y = __float2bfloat16(v.y - __bfloat162float(h1));
        lp1.x = __float2bfloat16(v.z - __bfloat162float(h2));
        lp1.y = __float2bfloat16(v.w - __bfloat162float(h3));
        *(__nv_bfloat162*)(lo + i)     = lp0;
        *(__nv_bfloat162*)(lo + i + 2) = lp1;
    }
}

// ---------------------------------------------------------------------------
// Tensor-core projection GEMM (unchanged from passing R14 kernel)
// ---------------------------------------------------------------------------
#define KCH 64
#define NCHUNK (DD / KCH)
#define TILE_B 16384
#define STAGE_B (4 * TILE_B)
#define GT_SMEM (1024 + 2 * STAGE_B)

__global__ __launch_bounds__(256) void gemm_tc(
    const __nv_bfloat16* __restrict__ ah, const __nv_bfloat16* __restrict__ al,
    const __nv_bfloat16* __restrict__ wh, const __nv_bfloat16* __restrict__ wl,
    const float* __restrict__ bias, float* __restrict__ C, int head_layout)
{
#ifdef HAS_TCGEN05
    extern __shared__ __align__(1024) char smem[];
    const uint32_t sb = smem_u32(smem);
    const int tid = threadIdx.x;
    const int wid = tid >> 5;
    const int lid = tid & 31;
    const int bx = blockIdx.x;
    const int by = blockIdx.y;

    if (wid == 0) TC_ALLOC(sb, 128);
    __syncthreads();
    uint32_t tmem;
    asm volatile("ld.shared.b32 %0, [%1];" : "=r"(tmem) : "r"(sb));
    if (tid == 0) { MBAR_INIT(sb + 8, 1); MBAR_INIT(sb + 16, 1); }
    if (wid == 0) TC_RELINQ();
    __syncthreads();

    const int row = tid >> 1;
    const int cb0 = (tid & 1) * 8;
    const __nv_bfloat16* pAh = ah + (size_t)(by * 128 + row) * DD + cb0;
    const __nv_bfloat16* pAl = al + (size_t)(by * 128 + row) * DD + cb0;
    const __nv_bfloat16* pBh = wh + (size_t)(bx * 128 + row) * DD + cb0;
    const __nv_bfloat16* pBl = wl + (size_t)(bx * 128 + row) * DD + cb0;
    const uint32_t bo = (uint32_t)(row * 128 + (tid & 1) * 16);

    for (int c = 0; c < NCHUNK; c++) {
        const int kc = c * KCH;
        const int stg = c & 1;
        uint4 va_h[4], va_l[4], vb_h[4], vb_l[4];
#pragma unroll
        for (int i = 0; i < 4; i++) {
            va_h[i] = *(const uint4*)(pAh + kc + 16 * i);
            va_l[i] = *(const uint4*)(pAl + kc + 16 * i);
            vb_h[i] = *(const uint4*)(pBh + kc + 16 * i);
            vb_l[i] = *(const uint4*)(pBl + kc + 16 * i);
        }
        if (c >= 2) {
            const uint32_t ph = (uint32_t)((c >> 1) - 1);
            MBAR_WAIT_PARITY(sb + 8 + 8 * stg, ph & 1);
        }
        char* st = smem + 1024 + stg * STAGE_B;
#pragma unroll
        for (int i = 0; i < 4; i++) {
            uint32_t off = bo + 32 * i;
            uint32_t sw = SMZ(off);
            *(uint4*)(st + sw)               = va_h[i];
            *(uint4*)(st + TILE_B + sw)      = va_l[i];
            *(uint4*)(st + 2 * TILE_B + sw)  = vb_h[i];
            *(uint4*)(st + 3 * TILE_B + sw)  = vb_l[i];
        }
        FENCE_ASYNC_SHARED();
        __syncthreads();
        if (wid == 0 && elect1()) {
            const uint32_t sa = sb + 1024 + stg * STAGE_B;
            const uint64_t dAh = make_desc(sa);
            const uint64_t dAl = make_desc(sa + TILE_B);
            const uint64_t dBh = make_desc(sa + 2 * TILE_B);
            const uint64_t dBl = make_desc(sa + 3 * TILE_B);
#pragma unroll
            for (int k = 0; k < 4; k++) {
                mma_bf16_ss(tmem, dAh + k * 2, dBh + k * 2, GT_IDESC,
                            (c == 0 && k == 0) ? 0u : 1u);
                mma_bf16_ss(tmem, dAh + k * 2, dBl + k * 2, GT_IDESC, 1u);
                mma_bf16_ss(tmem, dAl + k * 2, dBh + k * 2, GT_IDESC, 1u);
            }
            TC_COMMIT(sb + 8 + 8 * stg);
        }
    }
    MBAR_WAIT_PARITY(sb + 8,  (uint32_t)((NCHUNK / 2 - 1) & 1));
    MBAR_WAIT_PARITY(sb + 16, (uint32_t)((NCHUNK / 2 - 1) & 1));
    TC_FENCE_AFTER();

    if (wid < 4) {
        const int m = by * 128 + wid * 32 + lid;
        const int b_ = m >> 11;
        const int s = m & (SS - 1);
#pragma unroll
        for (int cb = 0; cb < 4; cb++) {
            uint32_t r[32];
            TC_LD_32X32B_X32(r, tmem + cb * 32);
            TC_WAIT_LD();
#pragma unroll
            for (int j = 0; j < 32; j++) {
                const int n = bx * 128 + cb * 32 + j;
                const float v = __uint_as_float(r[j]) + bias[n];
                if (head_layout) {
                    const int h = n >> 6;
                    const int hd = n & (HDD - 1);
                    C[(((size_t)b_ * HH + h) * SS + s) * HDD + hd] = v;
                } else {
                    C[(size_t)m * DD + n] = v;
                }
            }
        }
    }
    __syncthreads();
    if (tid == 0) { MBAR_INVAL(sb + 8); MBAR_INVAL(sb + 16); }
    __syncthreads();
    if (wid == 0) TC_DEALLOC(tmem, 128);
#endif
}

// ---------------------------------------------------------------------------
// Tensor-core fused attention, TWO-PASS softmax:
//  pass 1: per KV tile: K only -> QK^T -> LDTM -> exp -> rowsum (no stores)
//  pass 2: normalized P written directly (one P write), AV on normalized P
//          -> O comes out normalized; rescale pass deleted.
// m0 phases consumed immediately (counter over both passes); m1 1-lag.
// ---------------------------------------------------------------------------
#define AQH 1024
#define AQL (AQH + 16384)
#define AKH (AQL + 16384)
#define AKL (AKH + 8192)
#define AVH (AKL + 8192)
#define AVL (AVH + 8192)
#define APH (AVL + 8192)
#define APL (APH + 16384)
#define ARS (APL + 16384)          // 128 x 2 floats
#define AT_SMEM (ARS + 1024)       // 100352

__global__ __launch_bounds__(256) void attn_tc(
    const float* __restrict__ q, const float* __restrict__ k,
    const float* __restrict__ v, float* __restrict__ P,
    float* __restrict__ att)
{
#ifdef HAS_TCGEN05
    extern __shared__ __align__(1024) char smem[];
    const uint32_t sb = smem_u32(smem);
    float* rs = (float*)(smem + ARS);

    const int tid = threadIdx.x;
    const int wid = tid >> 5;
    const int lane = tid & 31;
    const int rt = (int)gridDim.x - 1 - (int)blockIdx.x;
    const int bh = blockIdx.y;
    const int r0 = rt * 128;

    const float* qb = q + (size_t)bh * SS * HDD;
    const float* kb = k + (size_t)bh * SS * HDD;
    const float* vb = v + (size_t)bh * SS * HDD;
    float* Pb = P + (size_t)bh * SS * SS;

    if (wid == 0) TC_ALLOC(sb, 128);
    __syncthreads();
    uint32_t tmem;
    asm volatile("ld.shared.b32 %0, [%1];" : "=r"(tmem) : "r"(sb));
    if (tid == 0) { MBAR_INIT(sb + 8, 1); MBAR_INIT(sb + 16, 1); }
    if (wid == 0) TC_RELINQ();

    // load Q tile [128 rows][64 hd] fp32 -> split bf16 K-major swizzled
    for (int i = tid; i < 128 * 16; i += 256) {
        const int row = i >> 4;
        const int c4 = (i & 15) << 2;
        float4 t = *(const float4*)(qb + (size_t)(r0 + row) * HDD + c4);
        uint32_t off = (uint32_t)(row * 128 + c4 * 2);
        uint32_t sw = SMZ(off);
        __nv_bfloat162 h01, h23, l01, l23;
        h01.x = __float2bfloat16(t.x); h01.y = __float2bfloat16(t.y);
        h23.x = __float2bfloat16(t.z); h23.y = __float2bfloat16(t.w);
        l01.x = __float2bfloat16(t.x - __bfloat162float(h01.x));
        l01.y = __float2bfloat16(t.y - __bfloat162float(h01.y));
        l23.x = __float2bfloat16(t.z - __bfloat162float(h23.x));
        l23.y = __float2bfloat16(t.w - __bfloat162float(h23.y));
        *(__nv_bfloat162*)(smem + AQH + sw)     = h01;
        *(__nv_bfloat162*)(smem + AQH + sw + 4) = h23;
        *(__nv_bfloat162*)(smem + AQL + sw)     = l01;
        *(__nv_bfloat162*)(smem + AQL + sw + 4) = l23;
    }
    __syncthreads();

    const int row = (wid & 3) * 32 + lane;   // TMEM lane = row
    const int half = wid >> 2;               // col half
    const int colbase = half * 32;

    const uint64_t dQh = make_desc(sb + AQH);
    const uint64_t dQl = make_desc(sb + AQL);
    const uint64_t dKh = make_desc(sb + AKH);
    const uint64_t dKl = make_desc(sb + AKL);
    const uint64_t dVh = make_desc(sb + AVH);
    const uint64_t dVl = make_desc(sb + AVL);
    const uint64_t dPh = make_desc(sb + APH);
    const uint64_t dPl = make_desc(sb + APL);

    const int njt = 2 * rt + 2;
    const int grow = r0 + row;
    int p0 = 0;                    // m0 phase counter (both passes)
    float rsum = 0.f;

    // ---------------- pass 1: row sums ----------------
    for (int jt = 0; jt < njt; jt++) {
        const int j0 = jt * 64;
        float4 tk[4];
#pragma unroll
        for (int it = 0; it < 4; it++) {
            const int i = tid + it * 256;
            tk[it] = *(const float4*)(kb + (size_t)(j0 + (i >> 4)) * HDD + ((i & 15) << 2));
        }
        // prior QK (tile jt-1) observed via m0 wait below -> safe to overwrite K smem
#pragma unroll
        for (int it = 0; it < 4; it++) {
            const int i = tid + it * 256;
            const int kr = i >> 4;
            const int c4 = (i & 15) << 2;
            uint32_t off = (uint32_t)(kr * 128 + c4 * 2);
            uint32_t sw = SMZ(off);
            __nv_bfloat162 h01, h23, l01, l23;
            h01.x = __float2bfloat16(tk[it].x); h01.y = __float2bfloat16(tk[it].y);
            h23.x = __float2bfloat16(tk[it].z); h23.y = __float2bfloat16(tk[it].w);
            l01.x = __float2bfloat16(tk[it].x - __bfloat162float(h01.x));
            l01.y = __float2bfloat16(tk[it].y - __bfloat162float(h01.y));
            l23.x = __float2bfloat16(tk[it].z - __bfloat162float(h23.x));
            l23.y = __float2bfloat16(tk[it].w - __bfloat162float(h23.y));
            *(__nv_bfloat162*)(smem + AKH + sw)     = h01;
            *(__nv_bfloat162*)(smem + AKH + sw + 4) = h23;
            *(__nv_bfloat162*)(smem + AKL + sw)     = l01;
            *(__nv_bfloat162*)(smem + AKL + sw + 4) = l23;
        }
        FENCE_ASYNC_SHARED();
        __syncthreads();

        if (wid == 0 && elect1()) {
#pragma unroll
            for (int kk = 0; kk < 4; kk++) {
                mma_bf16_ss(tmem, dQh + kk * 2, dKh + kk * 2, AT_IDESC,
                            (kk == 0) ? 0u : 1u);
                mma_bf16_ss(tmem, dQh + kk * 2, dKl + kk * 2, AT_IDESC, 1u);
                mma_bf16_ss(tmem, dQl + kk * 2, dKh + kk * 2, AT_IDESC, 1u);
            }
            TC_COMMIT(sb + 8);
        }
        MBAR_WAIT_PARITY(sb + 8, (uint32_t)(p0 & 1)); p0++;
        TC_FENCE_AFTER();

        uint32_t sr[32];
        TC_LD_32X32B_X32(sr, tmem + colbase);
        TC_WAIT_LD();
#pragma unroll
        for (int c = 0; c < 32; c++) {
            const int col = j0 + colbase + c;
            if (col <= grow) rsum += __expf(__uint_as_float(sr[c]) * 0.125f);
        }
        TC_FENCE_BEFORE();
        __syncthreads();   // all LDTM done before next tile's QK overwrites S
    }

    // combine row sums
    rs[row * 2 + half] = rsum;
    __syncthreads();
    const float invr = 1.0f / (rs[row * 2] + rs[row * 2 + 1]);
    __syncthreads();

    // ---------------- pass 2: normalized P + AV ----------------
    for (int jt = 0; jt < njt; jt++) {
        const int j0 = jt * 64;
        float4 tk[4], tv[4];
#pragma unroll
        for (int it = 0; it < 4; it++) {
            const int i = tid + it * 256;
            const int kr = i >> 4;
            const int c4 = (i & 15) << 2;
            tk[it] = *(const float4*)(kb + (size_t)(j0 + kr) * HDD + c4);
            tv[it] = *(const float4*)(vb + (size_t)(j0 + kr) * HDD + c4);
        }
        if (jt >= 1) MBAR_WAIT_PARITY(sb + 16, (uint32_t)((jt - 1) & 1));
#pragma unroll
        for (int it = 0; it < 4; it++) {
            const int i = tid + it * 256;
            const int kr = i >> 4;
            const int c4 = (i & 15) << 2;
            uint32_t off = (uint32_t)(kr * 128 + c4 * 2);
            uint32_t sw = SMZ(off);
            __nv_bfloat162 h01, h23, l01, l23;
            h01.x = __float2bfloat16(tk[it].x); h01.y = __float2bfloat16(tk[it].y);
            h23.x = __float2bfloat16(tk[it].z); h23.y = __float2bfloat16(tk[it].w);
            l01.x = __float2bfloat16(tk[it].x - __bfloat162float(h01.x));
            l01.y = __float2bfloat16(tk[it].y - __bfloat162float(h01.y));
            l23.x = __float2bfloat16(tk[it].z - __bfloat162float(h23.x));
            l23.y = __float2bfloat16(tk[it].w - __bfloat162float(h23.y));
            *(__nv_bfloat162*)(smem + AKH + sw)     = h01;
            *(__nv_bfloat162*)(smem + AKH + sw + 4) = h23;
            *(__nv_bfloat162*)(smem + AKL + sw)     = l01;
            *(__nv_bfloat162*)(smem + AKL + sw + 4) = l23;
            float ve[4] = {tv[it].x, tv[it].y, tv[it].z, tv[it].w};
#pragma unroll
            for (int e = 0; e < 4; e++) {
                const int d = c4 + e;
                uint32_t o2 = (uint32_t)(d * 128 + kr * 2);
                uint32_t s2 = SMZ(o2);
                __nv_bfloat16 hh = __float2bfloat16(ve[e]);
                *(__nv_bfloat16*)(smem + AVH + s2) = hh;
                *(__nv_bfloat16*)(smem + AVL + s2) =
                    __float2bfloat16(ve[e] - __bfloat162float(hh));
            }
        }
        FENCE_ASYNC_SHARED();
        __syncthreads();

        if (wid == 0 && elect1()) {
#pragma unroll
            for (int kk = 0; kk < 4; kk++) {
                mma_bf16_ss(tmem, dQh + kk * 2, dKh + kk * 2, AT_IDESC,
                            (kk == 0) ? 0u : 1u);
                mma_bf16_ss(tmem, dQh + kk * 2, dKl + kk * 2, AT_IDESC, 1u);
                mma_bf16_ss(tmem, dQl + kk * 2, dKh + kk * 2, AT_IDESC, 1u);
            }
            TC_COMMIT(sb + 8);
        }
        MBAR_WAIT_PARITY(sb + 8, (uint32_t)(p0 & 1)); p0++;
        TC_FENCE_AFTER();

        uint32_t sr[32];
        TC_LD_32X32B_X32(sr, tmem + colbase);
        TC_WAIT_LD();

        float pv[32];
#pragma unroll
        for (int c = 0; c < 32; c++) {
            const int col = j0 + colbase + c;
            pv[c] = (col <= grow)
                ? __expf(__uint_as_float(sr[c]) * 0.125f) * invr : 0.f;
        }
        // normalized P -> gmem (single write)
        {
            float* pg = Pb + (size_t)grow * SS + j0 + colbase;
#pragma unroll
            for (int c = 0; c < 32; c += 4)
                *(float4*)(pg + c) = make_float4(pv[c], pv[c+1], pv[c+2], pv[c+3]);
        }
        // split-bf16 normalized P -> smem
#pragma unroll
        for (int c = 0; c < 32; c += 2) {
            uint32_t off = (uint32_t)(row * 128 + (colbase + c) * 2);
            uint32_t sw = SMZ(off);
            __nv_bfloat162 hp, lp;
            hp.x = __float2bfloat16(pv[c]);
            hp.y = __float2bfloat16(pv[c + 1]);
            lp.x = __float2bfloat16(pv[c]     - __bfloat162float(hp.x));
            lp.y = __float2bfloat16(pv[c + 1] - __bfloat162float(hp.y));
            *(__nv_bfloat162*)(smem + APH + sw) = hp;
            *(__nv_bfloat162*)(smem + APL + sw) = lp;
        }
        TC_FENCE_BEFORE();
        FENCE_ASYNC_SHARED();
        __syncthreads();

        if (wid == 0 && elect1()) {
#pragma unroll
            for (int kk = 0; kk < 4; kk++) {
                mma_bf16_ss(tmem + 64, dPh + kk * 2, dVh + kk * 2, AT_IDESC,
                            (jt == 0 && kk == 0) ? 0u : 1u);
                mma_bf16_ss(tmem + 64, dPh + kk * 2, dVl + kk * 2, AT_IDESC, 1u);
                mma_bf16_ss(tmem + 64, dPl + kk * 2, dVh + kk * 2, AT_IDESC, 1u);
            }
            TC_COMMIT(sb + 16);
        }
    }
    MBAR_WAIT_PARITY(sb + 16, (uint32_t)((njt - 1) & 1));
    TC_FENCE_AFTER();

    // O already normalized: read + write att (B,S,D)
    {
        uint32_t orr[32];
        TC_LD_32X32B_X32(orr, tmem + 64 + colbase);
        TC_WAIT_LD();
        const int b_ = bh >> 4;
        const int h = bh & 15;
        float* ag = att + ((size_t)b_ * SS + grow) * DD + h * HDD + colbase;
#pragma unroll
        for (int c = 0; c < 32; c += 4)
            *(float4*)(ag + c) = make_float4(
                __uint_as_float(orr[c]),     __uint_as_float(orr[c + 1]),
                __uint_as_float(orr[c + 2]), __uint_as_float(orr[c + 3]));
    }
    __syncthreads();

    // zero-fill fully masked tiles
    {
        const int tx = tid & 15;
        const int ty = tid >> 4;
        const float4 z = make_float4(0.f, 0.f, 0.f, 0.f);
        for (int jt2 = njt; jt2 < SS / 64; jt2++) {
#pragma unroll
            for (int i = 0; i < 8; i++)
                *(float4*)(Pb + (size_t)(r0 + ty * 8 + i) * SS + jt2 * 64 + tx * 4) = z;
        }
    }
    __syncthreads();
    if (tid == 0) { MBAR_INVAL(sb + 8); MBAR_INVAL(sb + 16); }
    __syncthreads();
    if (wid == 0) TC_DEALLOC(tmem, 128);
#endif  // HAS_TCGEN05
}

// ---------------------------------------------------------------------------
// Launch
// ---------------------------------------------------------------------------
extern "C" void kernel_launch(void* const* d_in, const int* in_sizes, int n_in,
                              void* d_out, int out_size)
{
    const float* query = (const float*)d_in[0];
    const float* key_  = (const float*)d_in[1];
    const float* value = (const float*)d_in[2];
    const float* Wq = (const float*)d_in[4];
    const float* bq = (const float*)d_in[5];
    const float* Wk = (const float*)d_in[6];
    const float* bk = (const float*)d_in[7];
    const float* Wv = (const float*)d_in[8];
    const float* bv = (const float*)d_in[9];
    const float* Wo = (const float*)d_in[10];
    const float* bo = (const float*)d_in[11];
    float* out = (float*)d_out;

    float *q_, *k_, *v_, *att_, *Pfb_;
    __nv_bfloat16 *ah_, *al_, *wh_, *wl_;
    cudaGetSymbolAddress((void**)&q_,   g_q);
    cudaGetSymbolAddress((void**)&k_,   g_k);
    cudaGetSymbolAddress((void**)&v_,   g_v);
    cudaGetSymbolAddress((void**)&att_, g_att);
    cudaGetSymbolAddress((void**)&Pfb_, g_P);
    cudaGetSymbolAddress((void**)&ah_,  g_ah);
    cudaGetSymbolAddress((void**)&al_,  g_al);
    cudaGetSymbolAddress((void**)&wh_,  g_wh);
    cudaGetSymbolAddress((void**)&wl_,  g_wl);

    const size_t OUT0 = (size_t)BB * SS * DD;
    const size_t PE   = (size_t)BB * HH * SS * SS;
    float* P = ((size_t)out_size >= OUT0 + PE) ? (out + OUT0) : Pfb_;

    cudaFuncSetAttribute(gemm_tc, cudaFuncAttributeMaxDynamicSharedMemorySize,
                         GT_SMEM);
    cudaFuncSetAttribute(attn_tc, cudaFuncAttributeMaxDynamicSharedMemorySize,
                         AT_SMEM);

    const int NX = MM * DD;
    const int NW = DD * DD;
    dim3 gg(DD / 128, MM / 128);

    split_kernel<<<2048, 256>>>(query, ah_, al_, NX);
    split_kernel<<<512, 256>>>(Wq, wh_, wl_, NW);
    gemm_tc<<<gg, 256, GT_SMEM>>>(ah_, al_, wh_, wl_, bq, q_, 1);
    split_kernel<<<2048, 256>>>(key_, ah_, al_, NX);
    split_kernel<<<512, 256>>>(Wk, wh_, wl_, NW);
    gemm_tc<<<gg, 256, GT_SMEM>>>(ah_, al_, wh_, wl_, bk, k_, 1);
    split_kernel<<<2048, 256>>>(value, ah_, al_, NX);
    split_kernel<<<512, 256>>>(Wv, wh_, wl_, NW);
    gemm_tc<<<gg, 256, GT_SMEM>>>(ah_, al_, wh_, wl_, bv, v_, 1);

    dim3 gatt(SS / 128, BB * HH);   // (16, 32)
    attn_tc<<<gatt, 256, AT_SMEM>>>(q_, k_, v_, P, att_);

    split_kernel<<<2048, 256>>>(att_, ah_, al_, NX);
    split_kernel<<<512, 256>>>(Wo, wh_, wl_, NW);
    gemm_tc<<<gg, 256, GT_SMEM>>>(ah_, al_, wh_, wl_, bo, out, 0);
}